// round 6
// baseline (speedup 1.0000x reference)
#include <cuda_runtime.h>
#include <math.h>
#include <stdint.h>

// Problem constants (fixed shapes from reference setup_inputs)
#define T_STEPS 512
#define BATCH   128
#define MDIM    31
#define HID     512
#define EMB     256
#define SDIM    128
#define G3      (3*HID)          // 1536
#define TB      (T_STEPS*BATCH)  // 65536
#define BH      (BATCH*HID)      // 65536

#define SIGMA_MIN 0.01f
#define GAMMA     1.0f
#define LOG2PI    1.8378770664093453f

typedef unsigned long long ull;

// Scratch (device globals: no allocations allowed)
__device__ float g_phi[TB*EMB];                 //  67 MB
__device__ float g_xg [(size_t)TB*G3];          // 402 MB
__device__ float g_hs [(size_t)TB*HID];         // 134 MB  (hs[t] = h_t; hs[0]=0)
__device__ float g_loss[TB];                    // per-(t,b) loss, t>=1 written

// grid barrier state (self-resetting across launches)
__device__ unsigned          g_bar_cnt = 0;
__device__ volatile unsigned g_bar_gen = 0;

__device__ __forceinline__ float sigmoidf_(float v) {
    return 1.0f / (1.0f + expf(-v));
}

// packed fp32x2 ops (Blackwell f32x2 pipe)
__device__ __forceinline__ ull ffma2_(ull a, ull b, ull c) {
    ull d;
    asm("fma.rn.f32x2 %0, %1, %2, %3;" : "=l"(d) : "l"(a), "l"(b), "l"(c));
    return d;
}
__device__ __forceinline__ ull fadd2_(ull a, ull b) {
    ull d;
    asm("add.rn.f32x2 %0, %1, %2;" : "=l"(d) : "l"(a), "l"(b));
    return d;
}

__device__ __forceinline__ void cp_async8(uint32_t dst, const void* src) {
    asm volatile("cp.async.ca.shared.global [%0], [%1], 8;" :: "r"(dst), "l"(src));
}

// ---------------------------------------------------------------------------
// Kernel 0: zero h_0
// ---------------------------------------------------------------------------
__global__ void zero_h0_kernel() {
    int i = blockIdx.x * blockDim.x + threadIdx.x;
    if (i < BH) g_hs[i] = 0.0f;
}

// ---------------------------------------------------------------------------
// Kernel 1: phi = relu(x @ W_embed^T + b_embed)   [TB,31] -> [TB,256]
// ---------------------------------------------------------------------------
__global__ void phi_kernel(const float* __restrict__ x,
                           const float* __restrict__ W_embed,
                           const float* __restrict__ b_embed) {
    __shared__ float Ws[EMB * MDIM];
    __shared__ float Xs[16 * MDIM];

    const int tid  = threadIdx.x;      // 256 threads
    const int row0 = blockIdx.x * 16;

    for (int i = tid; i < EMB * MDIM; i += 256) Ws[i] = W_embed[i];
    for (int i = tid; i < 16 * MDIM;  i += 256) Xs[i] = x[row0 * MDIM + i];
    __syncthreads();

    const int e = tid;
    const float be = b_embed[e];
    #pragma unroll 4
    for (int r = 0; r < 16; ++r) {
        float acc = be;
        #pragma unroll
        for (int k = 0; k < MDIM; ++k)
            acc += Xs[r * MDIM + k] * Ws[e * MDIM + k];
        g_phi[(row0 + r) * EMB + e] = fmaxf(acc, 0.0f);
    }
}

// ---------------------------------------------------------------------------
// Kernel 2: x_gates = phi @ W_ih^T + b_ih   [TB,256] x [1536,256] -> [TB,1536]
// 128x128x16 tile, 256 threads, 8x8 microtile, packed f32x2 FMAs (k-pairs).
// ---------------------------------------------------------------------------
__global__ __launch_bounds__(256, 1)
void xg_kernel(const float* __restrict__ W_ih,
               const float* __restrict__ b_ih) {
    __shared__ float As[128][18];      // phi rows (M), k-major, padded
    __shared__ float Bs[128][18];      // W_ih rows (N), k-major, padded

    const int tid = threadIdx.x;       // 256
    const int tx = tid & 15;
    const int ty = tid >> 4;
    const int n0 = blockIdx.x * 128;   // over G3 (12 tiles)
    const int m0 = blockIdx.y * 128;   // over TB (512 tiles)

    ull c2[8][8];
    #pragma unroll
    for (int i = 0; i < 8; ++i)
        #pragma unroll
        for (int j = 0; j < 8; ++j) c2[i][j] = 0ull;

    for (int kc = 0; kc < EMB; kc += 16) {
        #pragma unroll
        for (int v = 0; v < 2; ++v) {
            const int idx = tid + v * 256;       // 0..511
            const int row = idx >> 2;
            const int col = (idx & 3) * 4;
            float4 a = *reinterpret_cast<const float4*>(
                &g_phi[(size_t)(m0 + row) * EMB + kc + col]);
            float4 b = *reinterpret_cast<const float4*>(
                &W_ih[(size_t)(n0 + row) * EMB + kc + col]);
            As[row][col+0] = a.x; As[row][col+1] = a.y;
            As[row][col+2] = a.z; As[row][col+3] = a.w;
            Bs[row][col+0] = b.x; Bs[row][col+1] = b.y;
            Bs[row][col+2] = b.z; Bs[row][col+3] = b.w;
        }
        __syncthreads();

        #pragma unroll
        for (int kp = 0; kp < 8; ++kp) {
            ull a[8], b[8];
            #pragma unroll
            for (int i = 0; i < 8; ++i)
                a[i] = *reinterpret_cast<const ull*>(&As[ty*8 + i][2*kp]);
            #pragma unroll
            for (int j = 0; j < 8; ++j)
                b[j] = *reinterpret_cast<const ull*>(&Bs[tx*8 + j][2*kp]);
            #pragma unroll
            for (int i = 0; i < 8; ++i)
                #pragma unroll
                for (int j = 0; j < 8; ++j)
                    c2[i][j] = ffma2_(a[i], b[j], c2[i][j]);
        }
        __syncthreads();
    }

    // Epilogue: collapse k-pair lanes, add bias, store
    float bias[8];
    #pragma unroll
    for (int j = 0; j < 8; ++j) bias[j] = b_ih[n0 + tx*8 + j];

    #pragma unroll
    for (int i = 0; i < 8; ++i) {
        const int m = m0 + ty*8 + i;
        float v[8];
        #pragma unroll
        for (int j = 0; j < 8; ++j) {
            union { ull u; float2 f; } u; u.u = c2[i][j];
            v[j] = u.f.x + u.f.y + bias[j];
        }
        float4* dst = reinterpret_cast<float4*>(&g_xg[(size_t)m * G3 + n0 + tx*8]);
        dst[0] = make_float4(v[0], v[1], v[2], v[3]);
        dst[1] = make_float4(v[4], v[5], v[6], v[7]);
    }
}

// ---------------------------------------------------------------------------
// Kernel 3: PERSISTENT GRU. One launch runs all 511 steps.
// 128 CTAs; CTA c owns j in [4c, 4c+4) for all 3 gates; W_hh slice cached in
// smem once. Per step: stream h_t via double-buffered cp.async chunks.
// Compute decomposition: 256 thr = 4 k-split groups x (4 j x 16 b-groups),
// each thread accumulates 3 gates x 8 b-rows over its k-quarter (FFMA2,
// 11 LDS.64 per 24 FFMA2). Partials reconciled per step through smem Racc
// with add.rn.f32x2, then a balanced 2-rows-per-thread gate epilogue.
// ---------------------------------------------------------------------------
#define GRU_CTAS 128
#define PADK 66        // h-row pad (floats): 8B-aligned rows
#define WPAD 514       // weight-row pad (floats)
#define BK   64        // k-chunk

#define HS_FLOATS   (12*WPAD + 2*BATCH*PADK)          // 23064 floats
#define RACC_ULL    (256*24)                          // 6144 ull = 49152 B
#define GRU_SMEM_BYTES (HS_FLOATS*4 + RACC_ULL*8)     // 92256 + 49152 = 141408

__device__ __forceinline__ void grid_barrier_() {
    __syncthreads();
    if (threadIdx.x == 0) {
        unsigned gen = g_bar_gen;
        if (atomicAdd(&g_bar_cnt, 1u) == GRU_CTAS - 1) {
            g_bar_cnt = 0;
            __threadfence();
            g_bar_gen = gen + 1;
        } else {
            while (g_bar_gen == gen) { __nanosleep(32); }
            __threadfence();
        }
    }
    __syncthreads();
}

__global__ __launch_bounds__(256, 1)
void gru_persistent_kernel(const float* __restrict__ W_hh,
                           const float* __restrict__ b_hh) {
    extern __shared__ float smem[];
    float* Ws  = smem;                    // [12][WPAD]
    float* Hs0 = smem + 12*WPAD;          // [BATCH][PADK]
    float* Hs1 = Hs0 + BATCH*PADK;
    ull*   Racc = reinterpret_cast<ull*>(smem + HS_FLOATS);  // [256][24]

    const int tid = threadIdx.x;
    // compute mapping
    const int ks    = tid >> 6;           // 0..3  k-split group
    const int local = tid & 63;
    const int jl    = local & 3;
    const int bB    = (local >> 2) * 8;   // first of 8 b-rows
    // epilogue mapping (2 b-rows per thread)
    const int ej  = blockIdx.x*4 + (tid & 3);
    const int eb0 = 2*(tid >> 2), eb1 = eb0 + 1;
    const int eloc = (tid & 3) + 4*(eb0 >> 3);
    const int ebb  = eb0 & 7;

    // Load this CTA's W_hh slice once: rows {g*HID + j} for g=0..2, jl=0..3
    for (int i = tid; i < 12*HID; i += 256) {
        int gj = i >> 9, k = i & (HID-1);
        int g = gj >> 2;
        int jj = blockIdx.x*4 + (gj & 3);
        Ws[gj*WPAD + k] = W_hh[((size_t)(g*HID + jj))*HID + k];
    }
    const float bhr = b_hh[ej];
    const float bhz = b_hh[HID + ej];
    const float bhn = b_hh[2*HID + ej];
    __syncthreads();

    const uint32_t s0 = (uint32_t)__cvta_generic_to_shared(Hs0);
    const uint32_t s1 = (uint32_t)__cvta_generic_to_shared(Hs1);

    // per-thread copy pattern: fixed 8B word kw, rows b = bb0 + 8*it
    const int kw  = tid & 31;             // 8B word index within 64-float chunk
    const int bb0 = tid >> 5;             // 0..7

    auto copy_chunk = [&](uint32_t sbuf, const float* hsrc, int kc) {
        const float* src = hsrc + (size_t)bb0*HID + kc + 2*kw;
        uint32_t dst = sbuf + (uint32_t)(bb0*PADK + 2*kw) * 4u;
        #pragma unroll
        for (int it = 0; it < 16; ++it) {
            cp_async8(dst, src);
            src += 8*HID;
            dst += 8*PADK*4;
        }
    };

    for (int t = 0; t < T_STEPS - 1; ++t) {
        const float* __restrict__ hsrc = g_hs + (size_t)t*BH;
        float*       __restrict__ hdst = g_hs + (size_t)(t+1)*BH;
        const float* __restrict__ xg   = g_xg + (size_t)t*BATCH*G3;

        // Prefetch epilogue operands (latency hidden by the k loop)
        const float xr0 = xg[(size_t)eb0*G3 + ej];
        const float xz0 = xg[(size_t)eb0*G3 + HID + ej];
        const float xn0 = xg[(size_t)eb0*G3 + 2*HID + ej];
        const float xr1 = xg[(size_t)eb1*G3 + ej];
        const float xz1 = xg[(size_t)eb1*G3 + HID + ej];
        const float xn1 = xg[(size_t)eb1*G3 + 2*HID + ej];
        const float hp0 = hsrc[(size_t)eb0*HID + ej];
        const float hp1 = hsrc[(size_t)eb1*HID + ej];

        copy_chunk(s0, hsrc, 0);
        asm volatile("cp.async.commit_group;");

        ull acc[3][8];
        #pragma unroll
        for (int g = 0; g < 3; ++g)
            #pragma unroll
            for (int bb = 0; bb < 8; ++bb) acc[g][bb] = 0ull;

        #pragma unroll 2
        for (int c = 0; c < HID/BK; ++c) {
            if (c < HID/BK - 1) {
                copy_chunk((c & 1) ? s0 : s1, hsrc, (c+1)*BK);
                asm volatile("cp.async.commit_group;");
                asm volatile("cp.async.wait_group 1;");
            } else {
                asm volatile("cp.async.wait_group 0;");
            }
            __syncthreads();

            const float* H  = (c & 1) ? Hs1 : Hs0;
            const float* Hb = H + bB*PADK + ks*16;
            const float* W0 = Ws + (0*4 + jl)*WPAD + c*BK + ks*16;
            const float* W1 = Ws + (1*4 + jl)*WPAD + c*BK + ks*16;
            const float* W2 = Ws + (2*4 + jl)*WPAD + c*BK + ks*16;

            #pragma unroll
            for (int kp = 0; kp < 8; ++kp) {
                const int kk = 2*kp;
                ull w0 = *reinterpret_cast<const ull*>(W0 + kk);
                ull w1 = *reinterpret_cast<const ull*>(W1 + kk);
                ull w2 = *reinterpret_cast<const ull*>(W2 + kk);
                ull h[8];
                #pragma unroll
                for (int bb = 0; bb < 8; ++bb)
                    h[bb] = *reinterpret_cast<const ull*>(Hb + bb*PADK + kk);
                #pragma unroll
                for (int bb = 0; bb < 8; ++bb) {
                    acc[0][bb] = ffma2_(h[bb], w0, acc[0][bb]);
                    acc[1][bb] = ffma2_(h[bb], w1, acc[1][bb]);
                    acc[2][bb] = ffma2_(h[bb], w2, acc[2][bb]);
                }
            }
            __syncthreads();
        }

        // Publish partials to smem: Racc[tid][g*8+bb]
        {
            ull* R = Racc + tid*24;
            #pragma unroll
            for (int g = 0; g < 3; ++g)
                #pragma unroll
                for (int bb = 0; bb < 8; ++bb) R[g*8 + bb] = acc[g][bb];
        }
        __syncthreads();

        // Epilogue: reconcile 4 k-split partials for 2 b-rows, gates, store
        float hg[3][2];
        #pragma unroll
        for (int g = 0; g < 3; ++g) {
            #pragma unroll
            for (int q = 0; q < 2; ++q) {
                const int idx = g*8 + ebb + q;
                ull s = fadd2_(fadd2_(Racc[(0*64 + eloc)*24 + idx],
                                      Racc[(1*64 + eloc)*24 + idx]),
                               fadd2_(Racc[(2*64 + eloc)*24 + idx],
                                      Racc[(3*64 + eloc)*24 + idx]));
                union { ull u; float2 f; } u; u.u = s;
                hg[g][q] = u.f.x + u.f.y;
            }
        }

        const float r0 = sigmoidf_(xr0 + hg[0][0] + bhr);
        const float z0 = sigmoidf_(xz0 + hg[1][0] + bhz);
        const float n0 = tanhf(xn0 + r0 * (hg[2][0] + bhn));
        hdst[(size_t)eb0*HID + ej] = (1.0f - z0) * n0 + z0 * hp0;

        const float r1 = sigmoidf_(xr1 + hg[0][1] + bhr);
        const float z1 = sigmoidf_(xz1 + hg[1][1] + bhz);
        const float n1 = tanhf(xn1 + r1 * (hg[2][1] + bhn));
        hdst[(size_t)eb1*HID + ej] = (1.0f - z1) * n1 + z1 * hp1;

        __threadfence();
        grid_barrier_();
    }
}

// ---------------------------------------------------------------------------
// Kernel 4: per-(t,b) loss for t>=1.
// ---------------------------------------------------------------------------
__global__ void loss_kernel(const float* __restrict__ x,
                            const float* __restrict__ tin,
                            const float* __restrict__ mask,
                            const float* __restrict__ W_he,
                            const float* __restrict__ b_he,
                            const float* __restrict__ W_mu,
                            const float* __restrict__ b_mu,
                            const float* __restrict__ W_lv,
                            const float* __restrict__ b_lv,
                            const float* __restrict__ h_inf,
                            const float* __restrict__ t_inf,
                            const float* __restrict__ b_int) {
    __shared__ float Hs[8][HID];
    __shared__ float Ws[SDIM][17];
    __shared__ float He[8][SDIM];
    __shared__ float red[8][32];

    const int tid    = threadIdx.x;    // 256
    const int r_base = BATCH + blockIdx.x * 8;

    for (int i = tid; i < 8 * HID; i += 256) {
        int rr = i >> 9, k = i & (HID - 1);
        Hs[rr][k] = g_hs[(size_t)(r_base + rr) * HID + k];
    }
    __syncthreads();

    const int s    = tid & 127;
    const int rgrp = tid >> 7;
    float acc[4] = {0.f, 0.f, 0.f, 0.f};

    for (int kc = 0; kc < HID; kc += 16) {
        for (int i = tid; i < SDIM * 16; i += 256) {
            int s2 = i >> 4, k = i & 15;
            Ws[s2][k] = W_he[(size_t)s2 * HID + kc + k];
        }
        __syncthreads();
        #pragma unroll
        for (int k = 0; k < 16; ++k) {
            float w = Ws[s][k];
            #pragma unroll
            for (int q = 0; q < 4; ++q)
                acc[q] += Hs[rgrp + 2*q][kc + k] * w;
        }
        __syncthreads();
    }
    {
        const float bs = b_he[s];
        #pragma unroll
        for (int q = 0; q < 4; ++q)
            He[rgrp + 2*q][s] = fmaxf(acc[q] + bs, 0.0f);
    }
    __syncthreads();

    if (tid < 8 * MDIM) {
        const int r = tid / MDIM;
        const int m = tid % MDIM;
        float mu = b_mu[m];
        float lv = b_lv[m];
        #pragma unroll 4
        for (int k = 0; k < SDIM; ++k) {
            const float he = He[r][k];
            mu += W_mu[m * SDIM + k] * he;
            lv += W_lv[m * SDIM + k] * he;
        }
        const float sigma = fmaxf(expf(0.5f * lv), SIGMA_MIN);
        const float xv = x[(size_t)(r_base + r) * MDIM + m];
        const float d = (xv - mu) / sigma;
        red[r][m] = -0.5f * d * d - logf(sigma) - 0.5f * LOG2PI;
    }
    __syncthreads();

    if (tid < 8) {
        const int r = tid;
        float marker_ll = 0.0f;
        for (int m = 0; m < MDIM; ++m) marker_ll += red[r][m];

        float past = 0.0f;
        for (int k = 0; k < SDIM; ++k) past += He[r][k] * h_inf[k];

        const float ti = t_inf[0];
        const float bi = b_int[0];
        const float tg = tin[(size_t)(r_base + r) * 2 + 1];
        const float term1 = past + ti * tg + bi;
        const float time_ll = term1 + (expf(past + bi) - expf(term1)) / ti;

        const int row = r_base + r;
        g_loss[row] = (GAMMA * (-time_ll) + (-marker_ll)) * mask[row];
    }
}

// ---------------------------------------------------------------------------
// Kernel 5: deterministic final reduction (double accumulation)
// ---------------------------------------------------------------------------
__global__ void reduce_kernel(float* __restrict__ out) {
    __shared__ double sd[256];
    const int tid = threadIdx.x;
    double sum = 0.0;
    for (int i = BATCH + tid; i < TB; i += 256) sum += (double)g_loss[i];
    sd[tid] = sum;
    __syncthreads();
    for (int off = 128; off > 0; off >>= 1) {
        if (tid < off) sd[tid] += sd[tid + off];
        __syncthreads();
    }
    if (tid == 0) out[0] = (float)sd[0];
}

// ---------------------------------------------------------------------------
extern "C" void kernel_launch(void* const* d_in, const int* in_sizes, int n_in,
                              void* d_out, int out_size) {
    (void)in_sizes; (void)n_in; (void)out_size;
    const float* x       = (const float*)d_in[0];
    const float* tin     = (const float*)d_in[1];
    const float* mask    = (const float*)d_in[2];
    const float* W_embed = (const float*)d_in[3];
    const float* b_embed = (const float*)d_in[4];
    const float* W_ih    = (const float*)d_in[5];
    const float* b_ih    = (const float*)d_in[6];
    const float* W_hh    = (const float*)d_in[7];
    const float* b_hh    = (const float*)d_in[8];
    const float* W_he    = (const float*)d_in[9];
    const float* b_he    = (const float*)d_in[10];
    const float* W_mu    = (const float*)d_in[11];
    const float* b_mu    = (const float*)d_in[12];
    const float* W_lv    = (const float*)d_in[13];
    const float* b_lv    = (const float*)d_in[14];
    const float* h_inf   = (const float*)d_in[15];
    const float* t_inf   = (const float*)d_in[16];
    const float* b_int   = (const float*)d_in[17];
    float* out = (float*)d_out;

    cudaFuncSetAttribute(gru_persistent_kernel,
                         cudaFuncAttributeMaxDynamicSharedMemorySize,
                         GRU_SMEM_BYTES);

    zero_h0_kernel<<<64, 1024>>>();
    phi_kernel<<<TB / 16, 256>>>(x, W_embed, b_embed);
    xg_kernel<<<dim3(G3 / 128, TB / 128), 256>>>(W_ih, b_ih);
    gru_persistent_kernel<<<GRU_CTAS, 256, GRU_SMEM_BYTES>>>(W_hh, b_hh);
    loss_kernel<<<(TB - BATCH) / 8, 256>>>(x, tin, mask, W_he, b_he,
                                           W_mu, b_mu, W_lv, b_lv,
                                           h_inf, t_inf, b_int);
    reduce_kernel<<<1, 256>>>(out);
}